// round 8
// baseline (speedup 1.0000x reference)
#include <cuda_runtime.h>
#include <math.h>

#define DIMS   2048
#define CONF_THRESH 0.5f
#define THREADS 512
#define NWARPS  16
#define GRID    148
#define ROWS_PER_TASK 64
#define NTASKS  256                          // 16384 / 64 exactly
#define PLANE_STRIDE 20                      // floats per k-row in a W plane (80B)
#define PLANE_FLOATS (512 * PLANE_STRIDE)    // 10240
#define WS_FLOATS    (4 * PLANE_FLOATS)      // 40960 floats = 160KB
#define FBUF_F4      (ROWS_PER_TASK * 32)    // float4 per stage buffer (64 rows x 512B)
#define SMEM_BYTES   (WS_FLOATS * 4 + 2 * FBUF_F4 * 16)   // 160KB + 64KB = 224KB

typedef unsigned long long ull;

__device__ __forceinline__ void cp16(unsigned dst_s, const void* src) {
    asm volatile("cp.async.cg.shared.global [%0], [%1], 16;"
                 :: "r"(dst_s), "l"(src) : "memory");
}

// One warp : 4 rows. Feature chunks staged to smem via cp.async double-buffer.
// k = c*128 + 4*lane + e. W in 4 e-planes, stride-20: LDS.128 conflict-free.
__global__ __launch_bounds__(THREADS, 1)
void det_kernel(const float4* __restrict__ feat4,   // [rows][512]
                const float*  __restrict__ W_bbox,  // [2048][12]
                const float*  __restrict__ W_conf,  // [2048][3]
                const float*  __restrict__ b_bbox,
                const float*  __restrict__ b_conf,
                float* __restrict__ out_boxes,      // [rows][3][4]
                float* __restrict__ out_conf,       // [rows][3]
                float* __restrict__ out_valid,      // [rows][3]
                int rows)
{
    extern __shared__ float ws[];                       // W planes: WS_FLOATS
    float4* fbuf = reinterpret_cast<float4*>(ws + WS_FLOATS);  // [2][64][32]

    // ---- Stage W into e-planes ----
    for (int i = threadIdx.x; i < DIMS * 16; i += THREADS) {
        int k = i >> 4, j = i & 15;
        float v = 0.0f;
        if (j < 12)      v = W_bbox[k * 12 + j];
        else if (j < 15) v = W_conf[k * 3 + (j - 12)];
        ws[(k & 3) * PLANE_FLOATS + (k >> 2) * PLANE_STRIDE + j] = v;
    }
    __syncthreads();

    int lane = threadIdx.x & 31;
    int warp = threadIdx.x >> 5;

    // Stage-role constants for this thread: it stages row 4*warp + lane/8,
    // float4 columns (lane&7) + 8q, q=0..3  (one 16B cp.async each).
    int srow    = 4 * warp + (lane >> 3);
    int scolb   = lane & 7;

    for (int task = blockIdx.x; task < NTASKS; task += GRID) {
        int row0 = task * ROWS_PER_TASK;
        const float4* srcbase = feat4 + (size_t)(row0 + srow) * (DIMS / 4) + scolb;

        // ---- prologue: stage chunks 0 and 1 ----
        #pragma unroll
        for (int pc = 0; pc < 2; pc++) {
            float4* dst = fbuf + pc * FBUF_F4 + srow * 32 + scolb;
            unsigned ds = (unsigned)__cvta_generic_to_shared(dst);
            const float4* src = srcbase + pc * 32;
            #pragma unroll
            for (int q = 0; q < 4; q++) cp16(ds + q * 128, src + q * 8);
            asm volatile("cp.async.commit_group;" ::: "memory");
        }

        ull acc[4][8];
        #pragma unroll
        for (int r = 0; r < 4; r++)
            #pragma unroll
            for (int p = 0; p < 8; p++) acc[r][p] = 0ULL;

        #pragma unroll 1
        for (int c = 0; c < 16; c++) {
            if (c < 14) asm volatile("cp.async.wait_group 1;" ::: "memory");
            else        asm volatile("cp.async.wait_group 0;" ::: "memory");
            __syncwarp();

            // Load this warp's 4 feature float4s for chunk c from smem
            const float4* fb = fbuf + (c & 1) * FBUF_F4 + (4 * warp) * 32 + lane;
            float4 fA[4];
            #pragma unroll
            for (int r = 0; r < 4; r++) fA[r] = fb[r * 32];

            int rowidx = (c * 32 + lane) * PLANE_STRIDE;
            #pragma unroll
            for (int e = 0; e < 4; e++) {
                const ulonglong2* wrow =
                    reinterpret_cast<const ulonglong2*>(ws + e * PLANE_FLOATS + rowidx);
                ulonglong2 w01 = wrow[0], w23 = wrow[1], w45 = wrow[2], w67 = wrow[3];
                ull w[8] = { w01.x, w01.y, w23.x, w23.y, w45.x, w45.y, w67.x, w67.y };

                #pragma unroll
                for (int r = 0; r < 4; r++) {
                    float fe = (e == 0) ? fA[r].x : (e == 1) ? fA[r].y
                             : (e == 2) ? fA[r].z : fA[r].w;
                    ull f2;
                    asm("mov.b64 %0, {%1, %1};" : "=l"(f2) : "r"(__float_as_uint(fe)));
                    #pragma unroll
                    for (int p = 0; p < 8; p++)
                        asm("fma.rn.f32x2 %0, %1, %2, %0;"
                            : "+l"(acc[r][p]) : "l"(f2), "l"(w[p]));
                }
            }

            // Stage chunk c+2 into the buffer we just finished consuming
            if (c + 2 < 16) {
                __syncwarp();   // all lanes done reading buf (c&1) before overwrite
                float4* dst = fbuf + (c & 1) * FBUF_F4 + srow * 32 + scolb;
                unsigned ds = (unsigned)__cvta_generic_to_shared(dst);
                const float4* src = srcbase + (c + 2) * 32;
                #pragma unroll
                for (int q = 0; q < 4; q++) cp16(ds + q * 128, src + q * 8);
                asm volatile("cp.async.commit_group;" ::: "memory");
            }
        }

        // ---- Unpack + butterfly reduce 15 partials/row over the warp ----
        float s[4][15];
        #pragma unroll
        for (int r = 0; r < 4; r++) {
            #pragma unroll
            for (int p = 0; p < 8; p++) {
                float lo = __uint_as_float((unsigned)(acc[r][p] & 0xFFFFFFFFULL));
                float hi = __uint_as_float((unsigned)(acc[r][p] >> 32));
                s[r][2 * p] = lo;
                if (2 * p + 1 < 15) s[r][2 * p + 1] = hi;
            }
        }
        #pragma unroll
        for (int off = 16; off >= 1; off >>= 1) {
            #pragma unroll
            for (int r = 0; r < 4; r++)
                #pragma unroll
                for (int j = 0; j < 15; j++)
                    s[r][j] += __shfl_xor_sync(0xFFFFFFFFu, s[r][j], off);
        }

        // ---- Epilogue: lanes 0..3 finalize rows ----
        if (lane < 4) {
            int row = row0 + 4 * warp + lane;

            float bbox[12];
            #pragma unroll
            for (int j = 0; j < 12; j++) bbox[j] = s[lane][j] + b_bbox[j];

            float conf[3];
            int   idx[3] = {0, 1, 2};
            #pragma unroll
            for (int a = 0; a < 3; a++) {
                float logit = s[lane][12 + a] + b_conf[a];
                conf[a] = 1.0f / (1.0f + expf(-logit));
            }

            if (conf[0] < conf[1]) { float tv = conf[0]; conf[0] = conf[1]; conf[1] = tv;
                                     int ti = idx[0]; idx[0] = idx[1]; idx[1] = ti; }
            if (conf[1] < conf[2]) { float tv = conf[1]; conf[1] = conf[2]; conf[2] = tv;
                                     int ti = idx[1]; idx[1] = idx[2]; idx[2] = ti; }
            if (conf[0] < conf[1]) { float tv = conf[0]; conf[0] = conf[1]; conf[1] = tv;
                                     int ti = idx[0]; idx[0] = idx[1]; idx[1] = ti; }

            #pragma unroll
            for (int slot = 0; slot < 3; slot++) {
                bool v = conf[slot] > CONF_THRESH;
                out_conf [row * 3 + slot] = conf[slot];
                out_valid[row * 3 + slot] = v ? 1.0f : 0.0f;
                #pragma unroll
                for (int i = 0; i < 4; i++)
                    out_boxes[row * 12 + slot * 4 + i] =
                        v ? bbox[idx[slot] * 4 + i] : 0.0f;
            }
        }
    }
}

extern "C" void kernel_launch(void* const* d_in, const int* in_sizes, int n_in,
                              void* d_out, int out_size) {
    const float* features = (const float*)d_in[0];
    const float* W_bbox   = (const float*)d_in[1];
    const float* b_bbox   = (const float*)d_in[2];
    const float* W_conf   = (const float*)d_in[3];
    const float* b_conf   = (const float*)d_in[4];

    int rows = in_sizes[0] / DIMS;   // 16384

    float* out       = (float*)d_out;
    float* out_boxes = out;
    float* out_conf  = out + (size_t)rows * 12;
    float* out_valid = out + (size_t)rows * 15;

    cudaFuncSetAttribute(det_kernel,
                         cudaFuncAttributeMaxDynamicSharedMemorySize, SMEM_BYTES);

    det_kernel<<<GRID, THREADS, SMEM_BYTES>>>((const float4*)features,
                                              W_bbox, W_conf, b_bbox, b_conf,
                                              out_boxes, out_conf, out_valid, rows);
}